// round 2
// baseline (speedup 1.0000x reference)
#include <cuda_runtime.h>
#include <cuda_bf16.h>
#include <math.h>

#define NN 100000
#define NEG_SLOPE 0.2f

// ---------------- scratch (device globals; no allocation allowed) ----------------
__device__ __align__(16) float    g_h1[NN * 64];      // layer1 linear out [N, 8*8]
__device__ __align__(16) float    g_as1[NN * 8];      // alpha_src layer1 [N, 8]
__device__ __align__(16) float    g_ad1[NN * 8];      // alpha_dst layer1 [N, 8]
__device__ __align__(16) unsigned g_m1[NN * 8];       // segment max (encoded) layer1
__device__ __align__(16) float    g_s1[NN * 8];       // segment sum layer1
__device__ __align__(16) float    g_agg1[NN * 64];    // unnormalized aggregate layer1
__device__ __align__(16) float    g_hmid[NN * 64];    // after bias + elu
__device__ __align__(16) float    g_h2[NN * 128];     // layer2 linear out
__device__ __align__(16) float    g_as2[NN];
__device__ __align__(16) float    g_ad2[NN];
__device__ __align__(16) unsigned g_m2[NN];
__device__ __align__(16) float    g_s2[NN];

// ---------------- helpers ----------------
__device__ __forceinline__ unsigned fenc(float f) {
    unsigned b = __float_as_uint(f);
    return (b & 0x80000000u) ? ~b : (b | 0x80000000u);
}
__device__ __forceinline__ float fdec(unsigned e) {
    return (e & 0x80000000u) ? __uint_as_float(e & 0x7FFFFFFFu)
                             : __uint_as_float(~e);
}
__device__ __forceinline__ float leaky(float v) {
    return v > 0.0f ? v : NEG_SLOPE * v;
}
__device__ __forceinline__ void red4(float* addr, float a, float b, float c, float d) {
    asm volatile("red.global.add.v4.f32 [%0], {%1,%2,%3,%4};"
                 :: "l"(addr), "f"(a), "f"(b), "f"(c), "f"(d) : "memory");
}
// edge_index is int32 (JAX x64 disabled: jnp.int64 request silently yields int32)
__device__ __forceinline__ void load_edge(const int* __restrict__ ei, int E,
                                          int idx, int& s, int& d) {
    if (idx < E) { s = ei[idx]; d = ei[E + idx]; }
    else         { s = d = idx - E; }          // self-loops appended
}

// ---------------- GEMM: C[M,Ncol] = A[M,K] @ B[K,Ncol], fp32 ----------------
// BM=64, BN=64, BK=32, 256 threads, 4x4 microtile per thread.
__global__ __launch_bounds__(256)
void gemm_kernel(const float* __restrict__ A, const float* __restrict__ B,
                 float* __restrict__ C, int M, int K, int Ncol) {
    __shared__ float As[32][68];   // transposed A tile: As[k][row]
    __shared__ float Bs[32][68];   // Bs[k][col]
    const int bm = blockIdx.x * 64;
    const int bn = blockIdx.y * 64;
    const int tid = threadIdx.x;
    const int tx = tid & 15;       // col group
    const int ty = tid >> 4;       // row group

    const int a_row  = tid >> 3;         // 0..31 (2 passes -> 64 rows)
    const int a_col4 = (tid & 7) * 4;    // 0..28
    const int b_row  = tid >> 4;         // 0..15 (2 passes -> 32 rows)
    const int b_col4 = (tid & 15) * 4;   // 0..60

    float acc[4][4];
#pragma unroll
    for (int i = 0; i < 4; i++)
#pragma unroll
        for (int j = 0; j < 4; j++) acc[i][j] = 0.0f;

    for (int k0 = 0; k0 < K; k0 += 32) {
#pragma unroll
        for (int p = 0; p < 2; p++) {
            int r = a_row + p * 32;
            int grow = bm + r;
            float4 v = make_float4(0.f, 0.f, 0.f, 0.f);
            if (grow < M)
                v = *(const float4*)&A[(size_t)grow * K + k0 + a_col4];
            As[a_col4 + 0][r] = v.x;
            As[a_col4 + 1][r] = v.y;
            As[a_col4 + 2][r] = v.z;
            As[a_col4 + 3][r] = v.w;
        }
#pragma unroll
        for (int p = 0; p < 2; p++) {
            int r = b_row + p * 16;
            float4 v = *(const float4*)&B[(size_t)(k0 + r) * Ncol + bn + b_col4];
            *(float4*)&Bs[r][b_col4] = v;
        }
        __syncthreads();
#pragma unroll
        for (int kk = 0; kk < 32; kk++) {
            float4 a = *(float4*)&As[kk][ty * 4];
            float4 b = *(float4*)&Bs[kk][tx * 4];
            acc[0][0] += a.x * b.x; acc[0][1] += a.x * b.y; acc[0][2] += a.x * b.z; acc[0][3] += a.x * b.w;
            acc[1][0] += a.y * b.x; acc[1][1] += a.y * b.y; acc[1][2] += a.y * b.z; acc[1][3] += a.y * b.w;
            acc[2][0] += a.z * b.x; acc[2][1] += a.z * b.y; acc[2][2] += a.z * b.z; acc[2][3] += a.z * b.w;
            acc[3][0] += a.w * b.x; acc[3][1] += a.w * b.y; acc[3][2] += a.w * b.z; acc[3][3] += a.w * b.w;
        }
        __syncthreads();
    }
#pragma unroll
    for (int i = 0; i < 4; i++) {
        int grow = bm + ty * 4 + i;
        if (grow < M) {
            float4 v = make_float4(acc[i][0], acc[i][1], acc[i][2], acc[i][3]);
            *(float4*)&C[(size_t)grow * Ncol + bn + tx * 4] = v;
        }
    }
}

// ---------------- layer1 alpha: per (node, head) dot over 8 channels ----------------
__global__ __launch_bounds__(256)
void alpha1_kernel(const float* __restrict__ att_src, const float* __restrict__ att_dst,
                   int nnodes) {
    int gid = blockIdx.x * blockDim.x + threadIdx.x;
    if (gid >= nnodes * 8) return;
    int n = gid >> 3, h = gid & 7;
    const float4* hp = (const float4*)&g_h1[n * 64 + h * 8];
    float4 h0 = hp[0], h1v = hp[1];
    const float4* sp = (const float4*)&att_src[h * 8];
    const float4* dp = (const float4*)&att_dst[h * 8];
    float4 s0 = sp[0], s1v = sp[1];
    float4 d0 = dp[0], d1v = dp[1];
    float as = h0.x * s0.x + h0.y * s0.y + h0.z * s0.z + h0.w * s0.w
             + h1v.x * s1v.x + h1v.y * s1v.y + h1v.z * s1v.z + h1v.w * s1v.w;
    float ad = h0.x * d0.x + h0.y * d0.y + h0.z * d0.z + h0.w * d0.w
             + h1v.x * d1v.x + h1v.y * d1v.y + h1v.z * d1v.z + h1v.w * d1v.w;
    g_as1[gid] = as;
    g_ad1[gid] = ad;
}

// ---------------- layer2 alpha: warp per node, 128-ch dot ----------------
__global__ __launch_bounds__(256)
void alpha2_kernel(const float* __restrict__ att_src, const float* __restrict__ att_dst,
                   int nnodes) {
    int gid = blockIdx.x * blockDim.x + threadIdx.x;
    int n = gid >> 5;
    int lane = gid & 31;
    if (n >= nnodes) return;
    float4 v = *(const float4*)&g_h2[(size_t)n * 128 + lane * 4];
    float4 a = ((const float4*)att_src)[lane];
    float4 b = ((const float4*)att_dst)[lane];
    float ss = v.x * a.x + v.y * a.y + v.z * a.z + v.w * a.w;
    float dd = v.x * b.x + v.y * b.y + v.z * b.z + v.w * b.w;
#pragma unroll
    for (int off = 16; off > 0; off >>= 1) {
        ss += __shfl_xor_sync(0xFFFFFFFFu, ss, off);
        dd += __shfl_xor_sync(0xFFFFFFFFu, dd, off);
    }
    if (lane == 0) { g_as2[n] = ss; g_ad2[n] = dd; }
}

// ---------------- layer1 edge passes ----------------
__global__ __launch_bounds__(256)
void edge_max1_kernel(const int* __restrict__ ei, int E, int Etot) {
    int idx = blockIdx.x * blockDim.x + threadIdx.x;
    if (idx >= Etot) return;
    int s, d; load_edge(ei, E, idx, s, d);
    const float4* ap = (const float4*)&g_as1[s * 8];
    const float4* bp = (const float4*)&g_ad1[d * 8];
    float4 a0 = ap[0], a1 = ap[1], b0 = bp[0], b1 = bp[1];
    float e[8] = { a0.x + b0.x, a0.y + b0.y, a0.z + b0.z, a0.w + b0.w,
                   a1.x + b1.x, a1.y + b1.y, a1.z + b1.z, a1.w + b1.w };
#pragma unroll
    for (int h = 0; h < 8; h++)
        atomicMax(&g_m1[d * 8 + h], fenc(leaky(e[h])));
}

__global__ __launch_bounds__(256)
void edge_sum1_kernel(const int* __restrict__ ei, int E, int Etot) {
    int idx = blockIdx.x * blockDim.x + threadIdx.x;
    if (idx >= Etot) return;
    int s, d; load_edge(ei, E, idx, s, d);
    const float4* ap = (const float4*)&g_as1[s * 8];
    const float4* bp = (const float4*)&g_ad1[d * 8];
    float4 a0 = ap[0], a1 = ap[1], b0 = bp[0], b1 = bp[1];
    float e[8] = { a0.x + b0.x, a0.y + b0.y, a0.z + b0.z, a0.w + b0.w,
                   a1.x + b1.x, a1.y + b1.y, a1.z + b1.z, a1.w + b1.w };
#pragma unroll
    for (int h = 0; h < 8; h++) {
        float p = __expf(leaky(e[h]) - fdec(g_m1[d * 8 + h]));
        atomicAdd(&g_s1[d * 8 + h], p);
    }
}

// 16 threads per edge; thread t handles channels 4t..4t+3 (head = t>>1)
__global__ __launch_bounds__(256)
void edge_agg1_kernel(const int* __restrict__ ei, int E, int Etot) {
    int gid = blockIdx.x * blockDim.x + threadIdx.x;
    int idx = gid >> 4;
    int t = gid & 15;
    if (idx >= Etot) return;
    int s, d; load_edge(ei, E, idx, s, d);
    int h = t >> 1;
    float e = leaky(g_as1[s * 8 + h] + g_ad1[d * 8 + h]);
    float w = __expf(e - fdec(g_m1[d * 8 + h]));
    float4 v = *(const float4*)&g_h1[s * 64 + t * 4];
    red4(&g_agg1[d * 64 + t * 4], w * v.x, w * v.y, w * v.z, w * v.w);
}

__global__ __launch_bounds__(256)
void finalize1_kernel(const float* __restrict__ b1, int nnodes) {
    int i = blockIdx.x * blockDim.x + threadIdx.x;
    if (i >= nnodes * 64) return;
    int n = i >> 6, c = i & 63;
    float v = g_agg1[i] / g_s1[n * 8 + (c >> 3)] + b1[c];
    g_hmid[i] = v > 0.0f ? v : expm1f(v);     // elu
}

// ---------------- layer2 edge passes ----------------
__global__ __launch_bounds__(256)
void edge_max2_kernel(const int* __restrict__ ei, int E, int Etot) {
    int idx = blockIdx.x * blockDim.x + threadIdx.x;
    if (idx >= Etot) return;
    int s, d; load_edge(ei, E, idx, s, d);
    float e = leaky(g_as2[s] + g_ad2[d]);
    atomicMax(&g_m2[d], fenc(e));
}

__global__ __launch_bounds__(256)
void edge_sum2_kernel(const int* __restrict__ ei, int E, int Etot) {
    int idx = blockIdx.x * blockDim.x + threadIdx.x;
    if (idx >= Etot) return;
    int s, d; load_edge(ei, E, idx, s, d);
    float e = leaky(g_as2[s] + g_ad2[d]);
    atomicAdd(&g_s2[d], __expf(e - fdec(g_m2[d])));
}

// warp per edge; lane handles channels 4*lane..4*lane+3; accumulates into d_out
__global__ __launch_bounds__(256)
void edge_agg2_kernel(const int* __restrict__ ei, int E, int Etot,
                      float* __restrict__ out) {
    int gid = blockIdx.x * blockDim.x + threadIdx.x;
    int idx = gid >> 5;
    int lane = gid & 31;
    if (idx >= Etot) return;
    int s, d; load_edge(ei, E, idx, s, d);
    float e = leaky(g_as2[s] + g_ad2[d]);
    float w = __expf(e - fdec(g_m2[d]));
    float4 v = *(const float4*)&g_h2[(size_t)s * 128 + lane * 4];
    red4(&out[(size_t)d * 128 + lane * 4], w * v.x, w * v.y, w * v.z, w * v.w);
}

__global__ __launch_bounds__(256)
void finalize2_kernel(const float* __restrict__ b2, float* __restrict__ out, int nnodes) {
    int i = blockIdx.x * blockDim.x + threadIdx.x;
    if (i >= nnodes * 128) return;
    int n = i >> 7, c = i & 127;
    out[i] = out[i] / g_s2[n] + b2[c];
}

// ---------------- launcher ----------------
extern "C" void kernel_launch(void* const* d_in, const int* in_sizes, int n_in,
                              void* d_out, int out_size) {
    const float* x        = (const float*)d_in[0];
    const int*   ei       = (const int*)d_in[1];      // int32 edge indices
    const float* W1       = (const float*)d_in[2];
    const float* att_src1 = (const float*)d_in[3];
    const float* att_dst1 = (const float*)d_in[4];
    const float* b1       = (const float*)d_in[5];
    const float* W2       = (const float*)d_in[6];
    const float* att_src2 = (const float*)d_in[7];
    const float* att_dst2 = (const float*)d_in[8];
    const float* b2       = (const float*)d_in[9];
    float* out = (float*)d_out;

    const int nnodes = in_sizes[0] / 512;   // 100000
    const int E      = in_sizes[1] / 2;     // 1600000
    const int Etot   = E + nnodes;

    // zero scratch accumulators (memset nodes are graph-capturable)
    void *pm1, *ps1, *pagg1, *pm2, *ps2;
    cudaGetSymbolAddress(&pm1, g_m1);
    cudaGetSymbolAddress(&ps1, g_s1);
    cudaGetSymbolAddress(&pagg1, g_agg1);
    cudaGetSymbolAddress(&pm2, g_m2);
    cudaGetSymbolAddress(&ps2, g_s2);
    cudaMemsetAsync(pm1,  0, (size_t)nnodes * 8 * 4);
    cudaMemsetAsync(ps1,  0, (size_t)nnodes * 8 * 4);
    cudaMemsetAsync(pagg1,0, (size_t)nnodes * 64 * 4);
    cudaMemsetAsync(pm2,  0, (size_t)nnodes * 4);
    cudaMemsetAsync(ps2,  0, (size_t)nnodes * 4);
    cudaMemsetAsync(d_out,0, (size_t)out_size * 4);

    float *h1_ptr, *hmid_ptr, *h2_ptr;
    cudaGetSymbolAddress((void**)&h1_ptr, g_h1);
    cudaGetSymbolAddress((void**)&hmid_ptr, g_hmid);
    cudaGetSymbolAddress((void**)&h2_ptr, g_h2);

    const int T = 256;
    dim3 g1grid((nnodes + 63) / 64, 1);
    gemm_kernel<<<g1grid, T>>>(x, W1, h1_ptr, nnodes, 512, 64);
    alpha1_kernel<<<(nnodes * 8 + T - 1) / T, T>>>(att_src1, att_dst1, nnodes);
    edge_max1_kernel<<<(Etot + T - 1) / T, T>>>(ei, E, Etot);
    edge_sum1_kernel<<<(Etot + T - 1) / T, T>>>(ei, E, Etot);
    edge_agg1_kernel<<<((size_t)Etot * 16 + T - 1) / T, T>>>(ei, E, Etot);
    finalize1_kernel<<<(nnodes * 64 + T - 1) / T, T>>>(b1, nnodes);

    dim3 g2grid((nnodes + 63) / 64, 2);
    gemm_kernel<<<g2grid, T>>>(hmid_ptr, W2, h2_ptr, nnodes, 64, 128);
    alpha2_kernel<<<((size_t)nnodes * 32 + T - 1) / T, T>>>(att_src2, att_dst2, nnodes);
    edge_max2_kernel<<<(Etot + T - 1) / T, T>>>(ei, E, Etot);
    edge_sum2_kernel<<<(Etot + T - 1) / T, T>>>(ei, E, Etot);
    edge_agg2_kernel<<<((size_t)Etot * 32 + T - 1) / T, T>>>(ei, E, Etot, out);
    finalize2_kernel<<<(nnodes * 128 + T - 1) / T, T>>>(b2, out, nnodes);
}

// round 3
// speedup vs baseline: 1.2221x; 1.2221x over previous
#include <cuda_runtime.h>
#include <cuda_bf16.h>
#include <math.h>

#define NN 100000
#define NEG_SLOPE 0.2f

// ---------------- scratch (device globals; no allocation allowed) ----------------
__device__ __align__(16) float g_h1[NN * 64];      // layer1 linear out [N, 8*8]
__device__ __align__(16) float g_as1[NN * 8];      // alpha_src layer1 [N, 8]
__device__ __align__(16) float g_ad1[NN * 8];      // alpha_dst layer1 [N, 8]
__device__ __align__(16) float g_s1[NN * 8];       // softmax denominator layer1
__device__ __align__(16) float g_agg1[NN * 64];    // unnormalized aggregate layer1
__device__ __align__(16) float g_hmid[NN * 64];    // after bias + elu
__device__ __align__(16) float g_h2[NN * 128];     // layer2 linear out
__device__ __align__(16) float g_as2[NN];
__device__ __align__(16) float g_ad2[NN];
__device__ __align__(16) float g_s2[NN];

// ---------------- helpers ----------------
__device__ __forceinline__ float leaky(float v) {
    return v > 0.0f ? v : NEG_SLOPE * v;
}
__device__ __forceinline__ void red4(float* addr, float a, float b, float c, float d) {
    asm volatile("red.global.add.v4.f32 [%0], {%1,%2,%3,%4};"
                 :: "l"(addr), "f"(a), "f"(b), "f"(c), "f"(d) : "memory");
}
__device__ __forceinline__ void red1(float* addr, float a) {
    asm volatile("red.global.add.f32 [%0], %1;" :: "l"(addr), "f"(a) : "memory");
}
// edge_index is int32
__device__ __forceinline__ void load_edge(const int* __restrict__ ei, int E,
                                          int idx, int& s, int& d) {
    if (idx < E) { s = ei[idx]; d = ei[E + idx]; }
    else         { s = d = idx - E; }          // self-loops appended
}

// ---------------- GEMM: C[M,Ncol] = A[M,K] @ B[K,Ncol], fp32 ----------------
// BM=64, BN=64, BK=32, 256 threads, 4x4 microtile per thread.
__global__ __launch_bounds__(256)
void gemm_kernel(const float* __restrict__ A, const float* __restrict__ B,
                 float* __restrict__ C, int M, int K, int Ncol) {
    __shared__ float As[32][68];   // transposed A tile: As[k][row]
    __shared__ float Bs[32][68];   // Bs[k][col]
    const int bm = blockIdx.x * 64;
    const int bn = blockIdx.y * 64;
    const int tid = threadIdx.x;
    const int tx = tid & 15;       // col group
    const int ty = tid >> 4;       // row group

    const int a_row  = tid >> 3;         // 0..31 (2 passes -> 64 rows)
    const int a_col4 = (tid & 7) * 4;    // 0..28
    const int b_row  = tid >> 4;         // 0..15 (2 passes -> 32 rows)
    const int b_col4 = (tid & 15) * 4;   // 0..60

    float acc[4][4];
#pragma unroll
    for (int i = 0; i < 4; i++)
#pragma unroll
        for (int j = 0; j < 4; j++) acc[i][j] = 0.0f;

    for (int k0 = 0; k0 < K; k0 += 32) {
#pragma unroll
        for (int p = 0; p < 2; p++) {
            int r = a_row + p * 32;
            int grow = bm + r;
            float4 v = make_float4(0.f, 0.f, 0.f, 0.f);
            if (grow < M)
                v = *(const float4*)&A[(size_t)grow * K + k0 + a_col4];
            As[a_col4 + 0][r] = v.x;
            As[a_col4 + 1][r] = v.y;
            As[a_col4 + 2][r] = v.z;
            As[a_col4 + 3][r] = v.w;
        }
#pragma unroll
        for (int p = 0; p < 2; p++) {
            int r = b_row + p * 16;
            float4 v = *(const float4*)&B[(size_t)(k0 + r) * Ncol + bn + b_col4];
            *(float4*)&Bs[r][b_col4] = v;
        }
        __syncthreads();
#pragma unroll
        for (int kk = 0; kk < 32; kk++) {
            float4 a = *(float4*)&As[kk][ty * 4];
            float4 b = *(float4*)&Bs[kk][tx * 4];
            acc[0][0] += a.x * b.x; acc[0][1] += a.x * b.y; acc[0][2] += a.x * b.z; acc[0][3] += a.x * b.w;
            acc[1][0] += a.y * b.x; acc[1][1] += a.y * b.y; acc[1][2] += a.y * b.z; acc[1][3] += a.y * b.w;
            acc[2][0] += a.z * b.x; acc[2][1] += a.z * b.y; acc[2][2] += a.z * b.z; acc[2][3] += a.z * b.w;
            acc[3][0] += a.w * b.x; acc[3][1] += a.w * b.y; acc[3][2] += a.w * b.z; acc[3][3] += a.w * b.w;
        }
        __syncthreads();
    }
#pragma unroll
    for (int i = 0; i < 4; i++) {
        int grow = bm + ty * 4 + i;
        if (grow < M) {
            float4 v = make_float4(acc[i][0], acc[i][1], acc[i][2], acc[i][3]);
            *(float4*)&C[(size_t)grow * Ncol + bn + tx * 4] = v;
        }
    }
}

// ---------------- layer1 alpha: per (node, head) dot over 8 channels ----------------
__global__ __launch_bounds__(256)
void alpha1_kernel(const float* __restrict__ att_src, const float* __restrict__ att_dst,
                   int nnodes) {
    int gid = blockIdx.x * blockDim.x + threadIdx.x;
    if (gid >= nnodes * 8) return;
    int n = gid >> 3, h = gid & 7;
    const float4* hp = (const float4*)&g_h1[n * 64 + h * 8];
    float4 h0 = hp[0], h1v = hp[1];
    const float4* sp = (const float4*)&att_src[h * 8];
    const float4* dp = (const float4*)&att_dst[h * 8];
    float4 s0 = sp[0], s1v = sp[1];
    float4 d0 = dp[0], d1v = dp[1];
    float as = h0.x * s0.x + h0.y * s0.y + h0.z * s0.z + h0.w * s0.w
             + h1v.x * s1v.x + h1v.y * s1v.y + h1v.z * s1v.z + h1v.w * s1v.w;
    float ad = h0.x * d0.x + h0.y * d0.y + h0.z * d0.z + h0.w * d0.w
             + h1v.x * d1v.x + h1v.y * d1v.y + h1v.z * d1v.z + h1v.w * d1v.w;
    g_as1[gid] = as;
    g_ad1[gid] = ad;
}

// ---------------- layer2 alpha: warp per node, 128-ch dot ----------------
__global__ __launch_bounds__(256)
void alpha2_kernel(const float* __restrict__ att_src, const float* __restrict__ att_dst,
                   int nnodes) {
    int gid = blockIdx.x * blockDim.x + threadIdx.x;
    int n = gid >> 5;
    int lane = gid & 31;
    if (n >= nnodes) return;
    float4 v = *(const float4*)&g_h2[(size_t)n * 128 + lane * 4];
    float4 a = ((const float4*)att_src)[lane];
    float4 b = ((const float4*)att_dst)[lane];
    float ss = v.x * a.x + v.y * a.y + v.z * a.z + v.w * a.w;
    float dd = v.x * b.x + v.y * b.y + v.z * b.z + v.w * b.w;
#pragma unroll
    for (int off = 16; off > 0; off >>= 1) {
        ss += __shfl_xor_sync(0xFFFFFFFFu, ss, off);
        dd += __shfl_xor_sync(0xFFFFFFFFu, dd, off);
    }
    if (lane == 0) { g_as2[n] = ss; g_ad2[n] = dd; }
}

// ---------------- layer1 fused edge pass: sum + aggregate ----------------
// 16 threads per edge; thread t handles channels 4t..4t+3 (head = t>>1).
// No max subtraction: logits are analytically bounded (|e| < ~4), exp is safe,
// and softmax is shift-invariant so the result is identical up to fp rounding.
__global__ __launch_bounds__(256)
void edge_agg1_kernel(const int* __restrict__ ei, int E, int Etot) {
    int gid = blockIdx.x * blockDim.x + threadIdx.x;
    int idx = gid >> 4;
    int t = gid & 15;
    if (idx >= Etot) return;
    int s, d; load_edge(ei, E, idx, s, d);
    int h = t >> 1;
    float e = leaky(g_as1[s * 8 + h] + g_ad1[d * 8 + h]);
    float w = __expf(e);
    if ((t & 1) == 0) red1(&g_s1[d * 8 + h], w);      // softmax denominator
    float4 v = *(const float4*)&g_h1[s * 64 + t * 4];
    red4(&g_agg1[d * 64 + t * 4], w * v.x, w * v.y, w * v.z, w * v.w);
}

__global__ __launch_bounds__(256)
void finalize1_kernel(const float* __restrict__ b1, int nnodes) {
    int i = blockIdx.x * blockDim.x + threadIdx.x;
    if (i >= nnodes * 64) return;
    int n = i >> 6, c = i & 63;
    float v = g_agg1[i] / g_s1[n * 8 + (c >> 3)] + b1[c];
    g_hmid[i] = v > 0.0f ? v : expm1f(v);     // elu
}

// ---------------- layer2 fused edge pass: sum + aggregate ----------------
// warp per edge; lane handles channels 4*lane..4*lane+3; accumulates into d_out
__global__ __launch_bounds__(256)
void edge_agg2_kernel(const int* __restrict__ ei, int E, int Etot,
                      float* __restrict__ out) {
    int gid = blockIdx.x * blockDim.x + threadIdx.x;
    int idx = gid >> 5;
    int lane = gid & 31;
    if (idx >= Etot) return;
    int s, d; load_edge(ei, E, idx, s, d);
    float e = leaky(g_as2[s] + g_ad2[d]);
    float w = __expf(e);
    if (lane == 0) red1(&g_s2[d], w);
    float4 v = *(const float4*)&g_h2[(size_t)s * 128 + lane * 4];
    red4(&out[(size_t)d * 128 + lane * 4], w * v.x, w * v.y, w * v.z, w * v.w);
}

__global__ __launch_bounds__(256)
void finalize2_kernel(const float* __restrict__ b2, float* __restrict__ out, int nnodes) {
    int i = blockIdx.x * blockDim.x + threadIdx.x;
    if (i >= nnodes * 128) return;
    int n = i >> 7, c = i & 127;
    out[i] = out[i] / g_s2[n] + b2[c];
}

// ---------------- launcher ----------------
extern "C" void kernel_launch(void* const* d_in, const int* in_sizes, int n_in,
                              void* d_out, int out_size) {
    const float* x        = (const float*)d_in[0];
    const int*   ei       = (const int*)d_in[1];      // int32 edge indices
    const float* W1       = (const float*)d_in[2];
    const float* att_src1 = (const float*)d_in[3];
    const float* att_dst1 = (const float*)d_in[4];
    const float* b1       = (const float*)d_in[5];
    const float* W2       = (const float*)d_in[6];
    const float* att_src2 = (const float*)d_in[7];
    const float* att_dst2 = (const float*)d_in[8];
    const float* b2       = (const float*)d_in[9];
    float* out = (float*)d_out;

    const int nnodes = in_sizes[0] / 512;   // 100000
    const int E      = in_sizes[1] / 2;     // 1600000
    const int Etot   = E + nnodes;

    // zero scratch accumulators (memset nodes are graph-capturable)
    void *ps1, *pagg1, *ps2;
    cudaGetSymbolAddress(&ps1, g_s1);
    cudaGetSymbolAddress(&pagg1, g_agg1);
    cudaGetSymbolAddress(&ps2, g_s2);
    cudaMemsetAsync(ps1,  0, (size_t)nnodes * 8 * 4);
    cudaMemsetAsync(pagg1,0, (size_t)nnodes * 64 * 4);
    cudaMemsetAsync(ps2,  0, (size_t)nnodes * 4);
    cudaMemsetAsync(d_out,0, (size_t)out_size * 4);

    float *h1_ptr, *hmid_ptr, *h2_ptr;
    cudaGetSymbolAddress((void**)&h1_ptr, g_h1);
    cudaGetSymbolAddress((void**)&hmid_ptr, g_hmid);
    cudaGetSymbolAddress((void**)&h2_ptr, g_h2);

    const int T = 256;
    dim3 g1grid((nnodes + 63) / 64, 1);
    gemm_kernel<<<g1grid, T>>>(x, W1, h1_ptr, nnodes, 512, 64);
    alpha1_kernel<<<(nnodes * 8 + T - 1) / T, T>>>(att_src1, att_dst1, nnodes);
    edge_agg1_kernel<<<((size_t)Etot * 16 + T - 1) / T, T>>>(ei, E, Etot);
    finalize1_kernel<<<(nnodes * 64 + T - 1) / T, T>>>(b1, nnodes);

    dim3 g2grid((nnodes + 63) / 64, 2);
    gemm_kernel<<<g2grid, T>>>(hmid_ptr, W2, h2_ptr, nnodes, 64, 128);
    alpha2_kernel<<<((size_t)nnodes * 32 + T - 1) / T, T>>>(att_src2, att_dst2, nnodes);
    edge_agg2_kernel<<<((size_t)Etot * 32 + T - 1) / T, T>>>(ei, E, Etot, out);
    finalize2_kernel<<<(nnodes * 128 + T - 1) / T, T>>>(b2, out, nnodes);
}

// round 4
// speedup vs baseline: 2.1526x; 1.7614x over previous
#include <cuda_runtime.h>
#include <cuda_bf16.h>
#include <math.h>

#define NN 100000
#define EMAX 1700000
#define NEG_SLOPE 0.2f

// ---------------- scratch (device globals) ----------------
__device__ __align__(16) float g_h1[NN * 64];      // layer1 linear out
__device__ __align__(16) float g_as1[NN * 8];
__device__ __align__(16) float g_ad1[NN * 8];
__device__ __align__(16) float g_hmid[NN * 64];    // after bias + elu
__device__ __align__(16) float g_h2[NN * 128];     // layer2 linear out
__device__ __align__(16) float g_as2[NN];
__device__ __align__(16) float g_ad2[NN];
// CSR by destination
__device__ int g_cnt[NN];        // histogram / scatter cursor
__device__ int g_off[NN + 1];    // exclusive offsets
__device__ int g_bsum[128];      // block sums for scan
__device__ int g_csr[EMAX];      // src node per incoming edge

// ---------------- helpers ----------------
__device__ __forceinline__ float leaky(float v) {
    return v > 0.0f ? v : NEG_SLOPE * v;
}
__device__ __forceinline__ void load_edge(const int* __restrict__ ei, int E,
                                          int idx, int& s, int& d) {
    if (idx < E) { s = ei[idx]; d = ei[E + idx]; }
    else         { s = d = idx - E; }          // self-loops appended
}

// ---------------- CSR build ----------------
__global__ __launch_bounds__(256)
void hist_kernel(const int* __restrict__ ei, int E, int Etot) {
    int idx = blockIdx.x * blockDim.x + threadIdx.x;
    if (idx >= Etot) return;
    int s, d; load_edge(ei, E, idx, s, d);
    atomicAdd(&g_cnt[d], 1);
}

// 256 threads scan 1024 elements (exclusive), per block
__global__ __launch_bounds__(256)
void scan1_kernel(int n) {
    __shared__ int wsum[8];
    int blk = blockIdx.x;
    int tid = threadIdx.x;
    int i = blk * 1024 + tid * 4;
    int a0 = (i + 0 < n) ? g_cnt[i + 0] : 0;
    int a1 = (i + 1 < n) ? g_cnt[i + 1] : 0;
    int a2 = (i + 2 < n) ? g_cnt[i + 2] : 0;
    int a3 = (i + 3 < n) ? g_cnt[i + 3] : 0;
    int tsum = a0 + a1 + a2 + a3;
    int lane = tid & 31, wid = tid >> 5;
    int sc = tsum;
#pragma unroll
    for (int off = 1; off < 32; off <<= 1) {
        int t = __shfl_up_sync(0xFFFFFFFFu, sc, off);
        if (lane >= off) sc += t;
    }
    if (lane == 31) wsum[wid] = sc;
    __syncthreads();
    if (wid == 0) {
        int ws = (lane < 8) ? wsum[lane] : 0;
#pragma unroll
        for (int off = 1; off < 8; off <<= 1) {
            int t = __shfl_up_sync(0xFFFFFFFFu, ws, off);
            if (lane >= off) ws += t;
        }
        if (lane < 8) wsum[lane] = ws;
    }
    __syncthreads();
    int excl = sc - tsum + (wid > 0 ? wsum[wid - 1] : 0);
    if (i + 0 < n) g_off[i + 0] = excl;
    if (i + 1 < n) g_off[i + 1] = excl + a0;
    if (i + 2 < n) g_off[i + 2] = excl + a0 + a1;
    if (i + 3 < n) g_off[i + 3] = excl + a0 + a1 + a2;
    if (tid == 255) g_bsum[blk] = excl + tsum;   // block total
}

__global__ void scan2_kernel(int nb, int n) {   // 1 thread; nb <= 128
    int acc = 0;
    for (int i = 0; i < nb; i++) { int t = g_bsum[i]; g_bsum[i] = acc; acc += t; }
    g_off[n] = acc;
}

__global__ __launch_bounds__(256)
void scan3_kernel(int n) {
    int i = blockIdx.x * blockDim.x + threadIdx.x;
    if (i < n) g_off[i] += g_bsum[i >> 10];
}

__global__ __launch_bounds__(256)
void scatter_kernel(const int* __restrict__ ei, int E, int Etot) {
    int idx = blockIdx.x * blockDim.x + threadIdx.x;
    if (idx >= Etot) return;
    int s, d; load_edge(ei, E, idx, s, d);
    int pos = g_off[d] + atomicAdd(&g_cnt[d], 1);   // g_cnt re-zeroed as cursor
    g_csr[pos] = s;
}

// ---------------- GEMM: C[M,Ncol] = A[M,K] @ B[K,Ncol], fp32 ----------------
// BM=128, BN=64, BK=16, 256 threads, 8x4 microtile per thread.
__global__ __launch_bounds__(256)
void gemm_kernel(const float* __restrict__ A, const float* __restrict__ B,
                 float* __restrict__ C, int M, int K, int Ncol) {
    __shared__ float As[16][132];   // As[k][row]
    __shared__ float Bs[16][68];    // Bs[k][col]
    const int bm = blockIdx.x * 128;
    const int bn = blockIdx.y * 64;
    const int tid = threadIdx.x;
    const int tx = tid & 15;        // col group (cols tx*4..tx*4+3)
    const int ty = tid >> 4;        // row group (rows ty*8..ty*8+7)

    const int a_row  = tid >> 2;          // 0..63 (2 passes -> 128 rows)
    const int a_col4 = (tid & 3) * 4;     // 0,4,8,12
    const int b_row  = tid >> 4;          // 0..15
    const int b_col4 = (tid & 15) * 4;    // 0..60

    float acc[8][4];
#pragma unroll
    for (int i = 0; i < 8; i++)
#pragma unroll
        for (int j = 0; j < 4; j++) acc[i][j] = 0.0f;

    for (int k0 = 0; k0 < K; k0 += 16) {
#pragma unroll
        for (int p = 0; p < 2; p++) {
            int r = a_row + p * 64;
            int grow = bm + r;
            float4 v = make_float4(0.f, 0.f, 0.f, 0.f);
            if (grow < M)
                v = *(const float4*)&A[(size_t)grow * K + k0 + a_col4];
            As[a_col4 + 0][r] = v.x;
            As[a_col4 + 1][r] = v.y;
            As[a_col4 + 2][r] = v.z;
            As[a_col4 + 3][r] = v.w;
        }
        {
            float4 v = *(const float4*)&B[(size_t)(k0 + b_row) * Ncol + bn + b_col4];
            *(float4*)&Bs[b_row][b_col4] = v;
        }
        __syncthreads();
#pragma unroll
        for (int kk = 0; kk < 16; kk++) {
            float4 a0 = *(float4*)&As[kk][ty * 8];
            float4 a1 = *(float4*)&As[kk][ty * 8 + 4];
            float4 b  = *(float4*)&Bs[kk][tx * 4];
            acc[0][0] += a0.x * b.x; acc[0][1] += a0.x * b.y; acc[0][2] += a0.x * b.z; acc[0][3] += a0.x * b.w;
            acc[1][0] += a0.y * b.x; acc[1][1] += a0.y * b.y; acc[1][2] += a0.y * b.z; acc[1][3] += a0.y * b.w;
            acc[2][0] += a0.z * b.x; acc[2][1] += a0.z * b.y; acc[2][2] += a0.z * b.z; acc[2][3] += a0.z * b.w;
            acc[3][0] += a0.w * b.x; acc[3][1] += a0.w * b.y; acc[3][2] += a0.w * b.z; acc[3][3] += a0.w * b.w;
            acc[4][0] += a1.x * b.x; acc[4][1] += a1.x * b.y; acc[4][2] += a1.x * b.z; acc[4][3] += a1.x * b.w;
            acc[5][0] += a1.y * b.x; acc[5][1] += a1.y * b.y; acc[5][2] += a1.y * b.z; acc[5][3] += a1.y * b.w;
            acc[6][0] += a1.z * b.x; acc[6][1] += a1.z * b.y; acc[6][2] += a1.z * b.z; acc[6][3] += a1.z * b.w;
            acc[7][0] += a1.w * b.x; acc[7][1] += a1.w * b.y; acc[7][2] += a1.w * b.z; acc[7][3] += a1.w * b.w;
        }
        __syncthreads();
    }
#pragma unroll
    for (int i = 0; i < 8; i++) {
        int grow = bm + ty * 8 + i;
        if (grow < M) {
            float4 v = make_float4(acc[i][0], acc[i][1], acc[i][2], acc[i][3]);
            *(float4*)&C[(size_t)grow * Ncol + bn + tx * 4] = v;
        }
    }
}

// ---------------- alpha kernels ----------------
__global__ __launch_bounds__(256)
void alpha1_kernel(const float* __restrict__ att_src, const float* __restrict__ att_dst,
                   int nnodes) {
    int gid = blockIdx.x * blockDim.x + threadIdx.x;
    if (gid >= nnodes * 8) return;
    int n = gid >> 3, h = gid & 7;
    const float4* hp = (const float4*)&g_h1[n * 64 + h * 8];
    float4 h0 = hp[0], h1v = hp[1];
    const float4* sp = (const float4*)&att_src[h * 8];
    const float4* dp = (const float4*)&att_dst[h * 8];
    float4 s0 = sp[0], s1v = sp[1];
    float4 d0 = dp[0], d1v = dp[1];
    float as = h0.x * s0.x + h0.y * s0.y + h0.z * s0.z + h0.w * s0.w
             + h1v.x * s1v.x + h1v.y * s1v.y + h1v.z * s1v.z + h1v.w * s1v.w;
    float ad = h0.x * d0.x + h0.y * d0.y + h0.z * d0.z + h0.w * d0.w
             + h1v.x * d1v.x + h1v.y * d1v.y + h1v.z * d1v.z + h1v.w * d1v.w;
    g_as1[gid] = as;
    g_ad1[gid] = ad;
}

__global__ __launch_bounds__(256)
void alpha2_kernel(const float* __restrict__ att_src, const float* __restrict__ att_dst,
                   int nnodes) {
    int gid = blockIdx.x * blockDim.x + threadIdx.x;
    int n = gid >> 5;
    int lane = gid & 31;
    if (n >= nnodes) return;
    float4 v = *(const float4*)&g_h2[(size_t)n * 128 + lane * 4];
    float4 a = ((const float4*)att_src)[lane];
    float4 b = ((const float4*)att_dst)[lane];
    float ss = v.x * a.x + v.y * a.y + v.z * a.z + v.w * a.w;
    float dd = v.x * b.x + v.y * b.y + v.z * b.z + v.w * b.w;
#pragma unroll
    for (int off = 16; off > 0; off >>= 1) {
        ss += __shfl_xor_sync(0xFFFFFFFFu, ss, off);
        dd += __shfl_xor_sync(0xFFFFFFFFu, dd, off);
    }
    if (lane == 0) { g_as2[n] = ss; g_ad2[n] = dd; }
}

// ---------------- layer1 aggregation: warp per destination node ----------------
// Lane l covers channels 2l, 2l+1 (head = l>>2). Softmax computed without max
// subtraction (logits analytically bounded, shift-invariant up to fp rounding).
__global__ __launch_bounds__(256)
void agg1_kernel(const float* __restrict__ b1, int nnodes) {
    int gw = (blockIdx.x * 256 + threadIdx.x) >> 5;
    int lane = threadIdx.x & 31;
    if (gw >= nnodes) return;
    int h = lane >> 2;
    float ad = g_ad1[gw * 8 + h];
    int beg = g_off[gw], end = g_off[gw + 1];
    float ax = 0.f, ay = 0.f, denom = 0.f;
    for (int j = beg; j < end; j++) {
        int s = g_csr[j];
        float w = __expf(leaky(g_as1[s * 8 + h] + ad));
        float2 v = *(const float2*)&g_h1[s * 64 + lane * 2];
        ax += w * v.x; ay += w * v.y; denom += w;
    }
    float inv = 1.0f / denom;
    int c = lane * 2;
    float o0 = ax * inv + b1[c];
    float o1 = ay * inv + b1[c + 1];
    o0 = o0 > 0.f ? o0 : expm1f(o0);
    o1 = o1 > 0.f ? o1 : expm1f(o1);
    *(float2*)&g_hmid[gw * 64 + c] = make_float2(o0, o1);
}

// ---------------- layer2 aggregation: warp per destination node ----------------
__global__ __launch_bounds__(256)
void agg2_kernel(const float* __restrict__ b2, float* __restrict__ out, int nnodes) {
    int gw = (blockIdx.x * 256 + threadIdx.x) >> 5;
    int lane = threadIdx.x & 31;
    if (gw >= nnodes) return;
    float ad = g_ad2[gw];
    int beg = g_off[gw], end = g_off[gw + 1];
    float4 acc = make_float4(0.f, 0.f, 0.f, 0.f);
    float denom = 0.f;
    for (int j = beg; j < end; j++) {
        int s = g_csr[j];
        float w = __expf(leaky(g_as2[s] + ad));
        float4 v = *(const float4*)&g_h2[(size_t)s * 128 + lane * 4];
        acc.x += w * v.x; acc.y += w * v.y; acc.z += w * v.z; acc.w += w * v.w;
        denom += w;
    }
    float inv = 1.0f / denom;
    float4 bb = ((const float4*)b2)[lane];
    float4 o = make_float4(acc.x * inv + bb.x, acc.y * inv + bb.y,
                           acc.z * inv + bb.z, acc.w * inv + bb.w);
    *(float4*)&out[(size_t)gw * 128 + lane * 4] = o;
}

// ---------------- launcher ----------------
extern "C" void kernel_launch(void* const* d_in, const int* in_sizes, int n_in,
                              void* d_out, int out_size) {
    const float* x        = (const float*)d_in[0];
    const int*   ei       = (const int*)d_in[1];
    const float* W1       = (const float*)d_in[2];
    const float* att_src1 = (const float*)d_in[3];
    const float* att_dst1 = (const float*)d_in[4];
    const float* b1       = (const float*)d_in[5];
    const float* W2       = (const float*)d_in[6];
    const float* att_src2 = (const float*)d_in[7];
    const float* att_dst2 = (const float*)d_in[8];
    const float* b2       = (const float*)d_in[9];
    float* out = (float*)d_out;

    const int nnodes = in_sizes[0] / 512;   // 100000
    const int E      = in_sizes[1] / 2;     // 1600000
    const int Etot   = E + nnodes;
    const int T = 256;
    const int NB = (nnodes + 1023) / 1024;  // scan blocks

    void* pcnt; cudaGetSymbolAddress(&pcnt, g_cnt);
    float *h1_ptr, *hmid_ptr, *h2_ptr;
    cudaGetSymbolAddress((void**)&h1_ptr, g_h1);
    cudaGetSymbolAddress((void**)&hmid_ptr, g_hmid);
    cudaGetSymbolAddress((void**)&h2_ptr, g_h2);

    // ---- CSR build (once; reused by both layers) ----
    cudaMemsetAsync(pcnt, 0, (size_t)nnodes * 4);
    hist_kernel<<<(Etot + T - 1) / T, T>>>(ei, E, Etot);
    scan1_kernel<<<NB, T>>>(nnodes);
    scan2_kernel<<<1, 1>>>(NB, nnodes);
    scan3_kernel<<<(nnodes + T - 1) / T, T>>>(nnodes);
    cudaMemsetAsync(pcnt, 0, (size_t)nnodes * 4);   // reuse as scatter cursor
    scatter_kernel<<<(Etot + T - 1) / T, T>>>(ei, E, Etot);

    // ---- layer 1 ----
    dim3 g1grid((nnodes + 127) / 128, 1);
    gemm_kernel<<<g1grid, T>>>(x, W1, h1_ptr, nnodes, 512, 64);
    alpha1_kernel<<<(nnodes * 8 + T - 1) / T, T>>>(att_src1, att_dst1, nnodes);
    agg1_kernel<<<((size_t)nnodes * 32 + T - 1) / T, T>>>(b1, nnodes);

    // ---- layer 2 ----
    dim3 g2grid((nnodes + 127) / 128, 2);
    gemm_kernel<<<g2grid, T>>>(hmid_ptr, W2, h2_ptr, nnodes, 64, 128);
    alpha2_kernel<<<((size_t)nnodes * 32 + T - 1) / T, T>>>(att_src2, att_dst2, nnodes);
    agg2_kernel<<<((size_t)nnodes * 32 + T - 1) / T, T>>>(b2, out, nnodes);
}

// round 5
// speedup vs baseline: 2.2055x; 1.0246x over previous
#include <cuda_runtime.h>
#include <cuda_bf16.h>
#include <math.h>

#define NN 100000
#define EMAX 1700000
#define NEG_SLOPE 0.2f

typedef unsigned long long u64;

// ---------------- scratch (device globals) ----------------
__device__ __align__(16) float g_h1[NN * 64];      // layer1 linear out
__device__ __align__(16) float g_as1[NN * 8];
__device__ __align__(16) float g_ad1[NN * 8];
__device__ __align__(16) float g_hmid[NN * 64];    // after bias + elu
__device__ __align__(16) float g_h2[NN * 128];     // layer2 linear out
__device__ __align__(16) float g_as2[NN];
__device__ __align__(16) float g_ad2[NN];
// CSR by destination
__device__ int g_cnt[NN];        // histogram / scatter cursor
__device__ int g_off[NN + 1];    // exclusive offsets
__device__ int g_bsum[128];      // block sums for scan
__device__ int g_csr[EMAX];      // src node per incoming edge

// ---------------- helpers ----------------
__device__ __forceinline__ float leaky(float v) {
    return v > 0.0f ? v : NEG_SLOPE * v;
}
__device__ __forceinline__ void load_edge(const int* __restrict__ ei, int E,
                                          int idx, int& s, int& d) {
    if (idx < E) { s = ei[idx]; d = ei[E + idx]; }
    else         { s = d = idx - E; }          // self-loops appended
}
__device__ __forceinline__ u64 pack2(float v) {          // (v, v) as f32x2
    u64 r; asm("mov.b64 %0, {%1, %1};" : "=l"(r) : "f"(v)); return r;
}
__device__ __forceinline__ void ffma2(u64& acc, u64 a, u64 b) {
    asm("fma.rn.f32x2 %0, %1, %2, %3;" : "=l"(acc) : "l"(a), "l"(b), "l"(acc));
}

// ---------------- CSR build ----------------
__global__ __launch_bounds__(256)
void hist_kernel(const int* __restrict__ ei, int E, int Etot) {
    int idx = blockIdx.x * blockDim.x + threadIdx.x;
    if (idx >= Etot) return;
    int s, d; load_edge(ei, E, idx, s, d);
    atomicAdd(&g_cnt[d], 1);
}

__global__ __launch_bounds__(256)
void scan1_kernel(int n) {
    __shared__ int wsum[8];
    int blk = blockIdx.x;
    int tid = threadIdx.x;
    int i = blk * 1024 + tid * 4;
    int a0 = (i + 0 < n) ? g_cnt[i + 0] : 0;
    int a1 = (i + 1 < n) ? g_cnt[i + 1] : 0;
    int a2 = (i + 2 < n) ? g_cnt[i + 2] : 0;
    int a3 = (i + 3 < n) ? g_cnt[i + 3] : 0;
    int tsum = a0 + a1 + a2 + a3;
    int lane = tid & 31, wid = tid >> 5;
    int sc = tsum;
#pragma unroll
    for (int off = 1; off < 32; off <<= 1) {
        int t = __shfl_up_sync(0xFFFFFFFFu, sc, off);
        if (lane >= off) sc += t;
    }
    if (lane == 31) wsum[wid] = sc;
    __syncthreads();
    if (wid == 0) {
        int ws = (lane < 8) ? wsum[lane] : 0;
#pragma unroll
        for (int off = 1; off < 8; off <<= 1) {
            int t = __shfl_up_sync(0xFFFFFFFFu, ws, off);
            if (lane >= off) ws += t;
        }
        if (lane < 8) wsum[lane] = ws;
    }
    __syncthreads();
    int excl = sc - tsum + (wid > 0 ? wsum[wid - 1] : 0);
    if (i + 0 < n) g_off[i + 0] = excl;
    if (i + 1 < n) g_off[i + 1] = excl + a0;
    if (i + 2 < n) g_off[i + 2] = excl + a0 + a1;
    if (i + 3 < n) g_off[i + 3] = excl + a0 + a1 + a2;
    if (tid == 255) g_bsum[blk] = excl + tsum;
}

__global__ void scan2_kernel(int nb, int n) {   // 1 thread; nb <= 128
    int acc = 0;
    for (int i = 0; i < nb; i++) { int t = g_bsum[i]; g_bsum[i] = acc; acc += t; }
    g_off[n] = acc;
}

__global__ __launch_bounds__(256)
void scan3_kernel(int n) {
    int i = blockIdx.x * blockDim.x + threadIdx.x;
    if (i < n) g_off[i] += g_bsum[i >> 10];
}

__global__ __launch_bounds__(256)
void scatter_kernel(const int* __restrict__ ei, int E, int Etot) {
    int idx = blockIdx.x * blockDim.x + threadIdx.x;
    if (idx >= Etot) return;
    int s, d; load_edge(ei, E, idx, s, d);
    int pos = g_off[d] + atomicAdd(&g_cnt[d], 1);
    g_csr[pos] = s;
}

// ---------------- GEMM: C[M,Ncol] = A[M,K] @ B[K,Ncol], fp32 (FFMA2) ----------
// BM=128, BN=64, BK=16, 256 threads. Per thread: 4 row-pairs x 4 cols,
// accumulated as f32x2 packed pairs (fma.rn.f32x2 -> SASS FFMA2, 2x fp32/issue).
__global__ __launch_bounds__(256)
void gemm_kernel(const float* __restrict__ A, const float* __restrict__ B,
                 float* __restrict__ C, int M, int K, int Ncol) {
    __shared__ float As[16][132];   // As[k][row]; row stride 528B (16B aligned)
    __shared__ float Bs[16][68];    // Bs[k][col]
    const int bm = blockIdx.x * 128;
    const int bn = blockIdx.y * 64;
    const int tid = threadIdx.x;
    const int tx = tid & 15;        // col group (cols tx*4..tx*4+3)
    const int ty = tid >> 4;        // row group (rows ty*8..ty*8+7)

    const int a_row  = tid >> 2;          // 0..63 (2 passes -> 128 rows)
    const int a_col4 = (tid & 3) * 4;     // 0,4,8,12
    const int b_row  = tid >> 4;          // 0..15
    const int b_col4 = (tid & 15) * 4;    // 0..60

    u64 acc[4][4];                  // [row_pair][col], each holds rows (2p, 2p+1)
#pragma unroll
    for (int p = 0; p < 4; p++)
#pragma unroll
        for (int j = 0; j < 4; j++) acc[p][j] = 0ULL;

    for (int k0 = 0; k0 < K; k0 += 16) {
#pragma unroll
        for (int pp = 0; pp < 2; pp++) {
            int r = a_row + pp * 64;
            int grow = bm + r;
            float4 v = make_float4(0.f, 0.f, 0.f, 0.f);
            if (grow < M)
                v = *(const float4*)&A[(size_t)grow * K + k0 + a_col4];
            As[a_col4 + 0][r] = v.x;
            As[a_col4 + 1][r] = v.y;
            As[a_col4 + 2][r] = v.z;
            As[a_col4 + 3][r] = v.w;
        }
        {
            float4 v = *(const float4*)&B[(size_t)(k0 + b_row) * Ncol + bn + b_col4];
            *(float4*)&Bs[b_row][b_col4] = v;
        }
        __syncthreads();
#pragma unroll
        for (int kk = 0; kk < 16; kk++) {
            u64 a0 = *(const u64*)&As[kk][ty * 8 + 0];   // rows pair (0,1)
            u64 a1 = *(const u64*)&As[kk][ty * 8 + 2];
            u64 a2 = *(const u64*)&As[kk][ty * 8 + 4];
            u64 a3 = *(const u64*)&As[kk][ty * 8 + 6];
            float4 b = *(const float4*)&Bs[kk][tx * 4];
            u64 b0 = pack2(b.x), b1 = pack2(b.y), b2 = pack2(b.z), b3 = pack2(b.w);
            ffma2(acc[0][0], a0, b0); ffma2(acc[0][1], a0, b1);
            ffma2(acc[0][2], a0, b2); ffma2(acc[0][3], a0, b3);
            ffma2(acc[1][0], a1, b0); ffma2(acc[1][1], a1, b1);
            ffma2(acc[1][2], a1, b2); ffma2(acc[1][3], a1, b3);
            ffma2(acc[2][0], a2, b0); ffma2(acc[2][1], a2, b1);
            ffma2(acc[2][2], a2, b2); ffma2(acc[2][3], a2, b3);
            ffma2(acc[3][0], a3, b0); ffma2(acc[3][1], a3, b1);
            ffma2(acc[3][2], a3, b2); ffma2(acc[3][3], a3, b3);
        }
        __syncthreads();
    }
#pragma unroll
    for (int p = 0; p < 4; p++) {
        float2 f0 = *(float2*)&acc[p][0];
        float2 f1 = *(float2*)&acc[p][1];
        float2 f2 = *(float2*)&acc[p][2];
        float2 f3 = *(float2*)&acc[p][3];
        int r0 = bm + ty * 8 + 2 * p;
        if (r0 < M)
            *(float4*)&C[(size_t)r0 * Ncol + bn + tx * 4] =
                make_float4(f0.x, f1.x, f2.x, f3.x);
        if (r0 + 1 < M)
            *(float4*)&C[(size_t)(r0 + 1) * Ncol + bn + tx * 4] =
                make_float4(f0.y, f1.y, f2.y, f3.y);
    }
}

// ---------------- alpha kernels ----------------
__global__ __launch_bounds__(256)
void alpha1_kernel(const float* __restrict__ att_src, const float* __restrict__ att_dst,
                   int nnodes) {
    int gid = blockIdx.x * blockDim.x + threadIdx.x;
    if (gid >= nnodes * 8) return;
    int n = gid >> 3, h = gid & 7;
    const float4* hp = (const float4*)&g_h1[n * 64 + h * 8];
    float4 h0 = hp[0], h1v = hp[1];
    const float4* sp = (const float4*)&att_src[h * 8];
    const float4* dp = (const float4*)&att_dst[h * 8];
    float4 s0 = sp[0], s1v = sp[1];
    float4 d0 = dp[0], d1v = dp[1];
    float as = h0.x * s0.x + h0.y * s0.y + h0.z * s0.z + h0.w * s0.w
             + h1v.x * s1v.x + h1v.y * s1v.y + h1v.z * s1v.z + h1v.w * s1v.w;
    float ad = h0.x * d0.x + h0.y * d0.y + h0.z * d0.z + h0.w * d0.w
             + h1v.x * d1v.x + h1v.y * d1v.y + h1v.z * d1v.z + h1v.w * d1v.w;
    g_as1[gid] = as;
    g_ad1[gid] = ad;
}

__global__ __launch_bounds__(256)
void alpha2_kernel(const float* __restrict__ att_src, const float* __restrict__ att_dst,
                   int nnodes) {
    int gid = blockIdx.x * blockDim.x + threadIdx.x;
    int n = gid >> 5;
    int lane = gid & 31;
    if (n >= nnodes) return;
    float4 v = *(const float4*)&g_h2[(size_t)n * 128 + lane * 4];
    float4 a = ((const float4*)att_src)[lane];
    float4 b = ((const float4*)att_dst)[lane];
    float ss = v.x * a.x + v.y * a.y + v.z * a.z + v.w * a.w;
    float dd = v.x * b.x + v.y * b.y + v.z * b.z + v.w * b.w;
#pragma unroll
    for (int off = 16; off > 0; off >>= 1) {
        ss += __shfl_xor_sync(0xFFFFFFFFu, ss, off);
        dd += __shfl_xor_sync(0xFFFFFFFFu, dd, off);
    }
    if (lane == 0) { g_as2[n] = ss; g_ad2[n] = dd; }
}

// ---------------- layer1 aggregation: warp per destination node ----------------
__global__ __launch_bounds__(256)
void agg1_kernel(const float* __restrict__ b1, int nnodes) {
    int gw = (blockIdx.x * 256 + threadIdx.x) >> 5;
    int lane = threadIdx.x & 31;
    if (gw >= nnodes) return;
    int h = lane >> 2;
    float ad = g_ad1[gw * 8 + h];
    int beg = g_off[gw], end = g_off[gw + 1];
    float ax = 0.f, ay = 0.f, denom = 0.f;
    for (int j = beg; j < end; j++) {
        int s = g_csr[j];
        float w = __expf(leaky(g_as1[s * 8 + h] + ad));
        float2 v = *(const float2*)&g_h1[s * 64 + lane * 2];
        ax += w * v.x; ay += w * v.y; denom += w;
    }
    float inv = 1.0f / denom;
    int c = lane * 2;
    float o0 = ax * inv + b1[c];
    float o1 = ay * inv + b1[c + 1];
    o0 = o0 > 0.f ? o0 : expm1f(o0);
    o1 = o1 > 0.f ? o1 : expm1f(o1);
    *(float2*)&g_hmid[gw * 64 + c] = make_float2(o0, o1);
}

// ---------------- layer2 aggregation: warp per destination node ----------------
__global__ __launch_bounds__(256)
void agg2_kernel(const float* __restrict__ b2, float* __restrict__ out, int nnodes) {
    int gw = (blockIdx.x * 256 + threadIdx.x) >> 5;
    int lane = threadIdx.x & 31;
    if (gw >= nnodes) return;
    float ad = g_ad2[gw];
    int beg = g_off[gw], end = g_off[gw + 1];
    float4 acc = make_float4(0.f, 0.f, 0.f, 0.f);
    float denom = 0.f;
    for (int j = beg; j < end; j++) {
        int s = g_csr[j];
        float w = __expf(leaky(g_as2[s] + ad));
        float4 v = *(const float4*)&g_h2[(size_t)s * 128 + lane * 4];
        acc.x += w * v.x; acc.y += w * v.y; acc.z += w * v.z; acc.w += w * v.w;
        denom += w;
    }
    float inv = 1.0f / denom;
    float4 bb = ((const float4*)b2)[lane];
    float4 o = make_float4(acc.x * inv + bb.x, acc.y * inv + bb.y,
                           acc.z * inv + bb.z, acc.w * inv + bb.w);
    *(float4*)&out[(size_t)gw * 128 + lane * 4] = o;
}

// ---------------- launcher ----------------
extern "C" void kernel_launch(void* const* d_in, const int* in_sizes, int n_in,
                              void* d_out, int out_size) {
    const float* x        = (const float*)d_in[0];
    const int*   ei       = (const int*)d_in[1];
    const float* W1       = (const float*)d_in[2];
    const float* att_src1 = (const float*)d_in[3];
    const float* att_dst1 = (const float*)d_in[4];
    const float* b1       = (const float*)d_in[5];
    const float* W2       = (const float*)d_in[6];
    const float* att_src2 = (const float*)d_in[7];
    const float* att_dst2 = (const float*)d_in[8];
    const float* b2       = (const float*)d_in[9];
    float* out = (float*)d_out;

    const int nnodes = in_sizes[0] / 512;   // 100000
    const int E      = in_sizes[1] / 2;     // 1600000
    const int Etot   = E + nnodes;
    const int T = 256;
    const int NB = (nnodes + 1023) / 1024;

    void* pcnt; cudaGetSymbolAddress(&pcnt, g_cnt);
    float *h1_ptr, *hmid_ptr, *h2_ptr;
    cudaGetSymbolAddress((void**)&h1_ptr, g_h1);
    cudaGetSymbolAddress((void**)&hmid_ptr, g_hmid);
    cudaGetSymbolAddress((void**)&h2_ptr, g_h2);

    // ---- CSR build (once; reused by both layers) ----
    cudaMemsetAsync(pcnt, 0, (size_t)nnodes * 4);
    hist_kernel<<<(Etot + T - 1) / T, T>>>(ei, E, Etot);
    scan1_kernel<<<NB, T>>>(nnodes);
    scan2_kernel<<<1, 1>>>(NB, nnodes);
    scan3_kernel<<<(nnodes + T - 1) / T, T>>>(nnodes);
    cudaMemsetAsync(pcnt, 0, (size_t)nnodes * 4);
    scatter_kernel<<<(Etot + T - 1) / T, T>>>(ei, E, Etot);

    // ---- layer 1 ----
    dim3 g1grid((nnodes + 127) / 128, 1);
    gemm_kernel<<<g1grid, T>>>(x, W1, h1_ptr, nnodes, 512, 64);
    alpha1_kernel<<<(nnodes * 8 + T - 1) / T, T>>>(att_src1, att_dst1, nnodes);
    agg1_kernel<<<((size_t)nnodes * 32 + T - 1) / T, T>>>(b1, nnodes);

    // ---- layer 2 ----
    dim3 g2grid((nnodes + 127) / 128, 2);
    gemm_kernel<<<g2grid, T>>>(hmid_ptr, W2, h2_ptr, nnodes, 64, 128);
    alpha2_kernel<<<((size_t)nnodes * 32 + T - 1) / T, T>>>(att_src2, att_dst2, nnodes);
    agg2_kernel<<<((size_t)nnodes * 32 + T - 1) / T, T>>>(b2, out, nnodes);
}

// round 6
// speedup vs baseline: 2.4726x; 1.1211x over previous
#include <cuda_runtime.h>
#include <cuda_bf16.h>
#include <math.h>

#define NN 100000
#define EMAX 1700000
#define NEG_SLOPE 0.2f

typedef unsigned long long u64;

// ---------------- scratch (device globals) ----------------
__device__ __align__(16) float g_h1[NN * 64];
__device__ __align__(16) float g_as1[NN * 8];
__device__ __align__(16) float g_ad1[NN * 8];
__device__ __align__(16) float g_hmid[NN * 64];
__device__ __align__(16) float g_h2[NN * 128];
__device__ __align__(16) float g_as2[NN];
__device__ __align__(16) float g_ad2[NN];
// CSR by destination
__device__ int g_cnt[NN];
__device__ int g_off[NN + 1];
__device__ int g_bsum[128];
__device__ int g_csr[EMAX];

// ---------------- helpers ----------------
__device__ __forceinline__ float leaky(float v) {
    return v > 0.0f ? v : NEG_SLOPE * v;
}
__device__ __forceinline__ void load_edge(const int* __restrict__ ei, int E,
                                          int idx, int& s, int& d) {
    if (idx < E) { s = ei[idx]; d = ei[E + idx]; }
    else         { s = d = idx - E; }
}
__device__ __forceinline__ u64 pack2(float v) {
    u64 r; asm("mov.b64 %0, {%1, %1};" : "=l"(r) : "f"(v)); return r;
}
__device__ __forceinline__ void ffma2(u64& acc, u64 a, u64 b) {
    asm("fma.rn.f32x2 %0, %1, %2, %3;" : "=l"(acc) : "l"(a), "l"(b), "l"(acc));
}

// ---------------- CSR build ----------------
__global__ __launch_bounds__(256)
void hist_kernel(const int* __restrict__ ei, int E, int Etot) {
    int idx = blockIdx.x * blockDim.x + threadIdx.x;
    if (idx >= Etot) return;
    int s, d; load_edge(ei, E, idx, s, d);
    atomicAdd(&g_cnt[d], 1);
}

__global__ __launch_bounds__(256)
void scan1_kernel(int n) {
    __shared__ int wsum[8];
    int blk = blockIdx.x;
    int tid = threadIdx.x;
    int i = blk * 1024 + tid * 4;
    int a0 = (i + 0 < n) ? g_cnt[i + 0] : 0;
    int a1 = (i + 1 < n) ? g_cnt[i + 1] : 0;
    int a2 = (i + 2 < n) ? g_cnt[i + 2] : 0;
    int a3 = (i + 3 < n) ? g_cnt[i + 3] : 0;
    int tsum = a0 + a1 + a2 + a3;
    int lane = tid & 31, wid = tid >> 5;
    int sc = tsum;
#pragma unroll
    for (int off = 1; off < 32; off <<= 1) {
        int t = __shfl_up_sync(0xFFFFFFFFu, sc, off);
        if (lane >= off) sc += t;
    }
    if (lane == 31) wsum[wid] = sc;
    __syncthreads();
    if (wid == 0) {
        int ws = (lane < 8) ? wsum[lane] : 0;
#pragma unroll
        for (int off = 1; off < 8; off <<= 1) {
            int t = __shfl_up_sync(0xFFFFFFFFu, ws, off);
            if (lane >= off) ws += t;
        }
        if (lane < 8) wsum[lane] = ws;
    }
    __syncthreads();
    int excl = sc - tsum + (wid > 0 ? wsum[wid - 1] : 0);
    if (i + 0 < n) g_off[i + 0] = excl;
    if (i + 1 < n) g_off[i + 1] = excl + a0;
    if (i + 2 < n) g_off[i + 2] = excl + a0 + a1;
    if (i + 3 < n) g_off[i + 3] = excl + a0 + a1 + a2;
    if (tid == 255) g_bsum[blk] = excl + tsum;
}

// single-warp scan over <=128 block sums (replaces serial 1-thread version)
__global__ void scan2_kernel(int nb, int n) {
    int lane = threadIdx.x & 31;
    int v[4]; int s = 0;
#pragma unroll
    for (int i = 0; i < 4; i++) {
        int idx = lane * 4 + i;
        v[i] = (idx < nb) ? g_bsum[idx] : 0;
        s += v[i];
    }
    int sc = s;
#pragma unroll
    for (int off = 1; off < 32; off <<= 1) {
        int t = __shfl_up_sync(0xFFFFFFFFu, sc, off);
        if (lane >= off) sc += t;
    }
    int run = sc - s;   // exclusive prefix
#pragma unroll
    for (int i = 0; i < 4; i++) {
        int idx = lane * 4 + i;
        int t = v[i];
        if (idx < nb) g_bsum[idx] = run;
        run += t;
    }
    if (lane == 31) g_off[n] = run;   // grand total
}

__global__ __launch_bounds__(256)
void scan3_kernel(int n) {
    int i = blockIdx.x * blockDim.x + threadIdx.x;
    if (i < n) g_off[i] += g_bsum[i >> 10];
}

__global__ __launch_bounds__(256)
void scatter_kernel(const int* __restrict__ ei, int E, int Etot) {
    int idx = blockIdx.x * blockDim.x + threadIdx.x;
    if (idx >= Etot) return;
    int s, d; load_edge(ei, E, idx, s, d);
    int pos = g_off[d] + atomicAdd(&g_cnt[d], 1);
    g_csr[pos] = s;
}

// ---------------- GEMM: C[M,Ncol] = A[M,K] @ B[K,Ncol], fp32 (FFMA2) ----------
// BM=128, BN=64, BK=16, 256 threads, 4 row-pairs x 4 cols per thread.
// Register double-buffered global loads; A operands via LDS.128 (ulonglong2).
__global__ __launch_bounds__(256)
void gemm_kernel(const float* __restrict__ A, const float* __restrict__ B,
                 float* __restrict__ C, int M, int K, int Ncol) {
    __shared__ float As[16][132];   // As[k][row]
    __shared__ float Bs[16][68];    // Bs[k][col]
    const int bm = blockIdx.x * 128;
    const int bn = blockIdx.y * 64;
    const int tid = threadIdx.x;
    const int tx = tid & 15;
    const int ty = tid >> 4;

    const int a_row  = tid >> 2;          // 0..63 (+64 second pass)
    const int a_col4 = (tid & 3) * 4;     // 0,4,8,12
    const int b_row  = tid >> 4;          // 0..15
    const int b_col4 = (tid & 15) * 4;    // 0..60

    const int grow0 = bm + a_row;
    const int grow1 = bm + a_row + 64;

    u64 acc[4][4];
#pragma unroll
    for (int p = 0; p < 4; p++)
#pragma unroll
        for (int j = 0; j < 4; j++) acc[p][j] = 0ULL;

    // prefetch tile 0
    float4 pa0 = make_float4(0.f,0.f,0.f,0.f), pa1 = pa0, pb;
    if (grow0 < M) pa0 = *(const float4*)&A[(size_t)grow0 * K + a_col4];
    if (grow1 < M) pa1 = *(const float4*)&A[(size_t)grow1 * K + a_col4];
    pb = *(const float4*)&B[(size_t)b_row * Ncol + bn + b_col4];

    for (int k0 = 0; k0 < K; k0 += 16) {
        // store prefetched tile to smem
        As[a_col4 + 0][a_row] = pa0.x;
        As[a_col4 + 1][a_row] = pa0.y;
        As[a_col4 + 2][a_row] = pa0.z;
        As[a_col4 + 3][a_row] = pa0.w;
        As[a_col4 + 0][a_row + 64] = pa1.x;
        As[a_col4 + 1][a_row + 64] = pa1.y;
        As[a_col4 + 2][a_row + 64] = pa1.z;
        As[a_col4 + 3][a_row + 64] = pa1.w;
        *(float4*)&Bs[b_row][b_col4] = pb;
        __syncthreads();

        // prefetch next tile (LDG latency overlaps compute below)
        int kn = k0 + 16;
        if (kn < K) {
            if (grow0 < M) pa0 = *(const float4*)&A[(size_t)grow0 * K + kn + a_col4];
            if (grow1 < M) pa1 = *(const float4*)&A[(size_t)grow1 * K + kn + a_col4];
            pb = *(const float4*)&B[(size_t)(kn + b_row) * Ncol + bn + b_col4];
        }

#pragma unroll
        for (int kk = 0; kk < 16; kk++) {
            ulonglong2 A01 = *(const ulonglong2*)&As[kk][ty * 8];       // pairs (0,1),(2,3)
            ulonglong2 A23 = *(const ulonglong2*)&As[kk][ty * 8 + 4];   // pairs (4,5),(6,7)
            float4 b = *(const float4*)&Bs[kk][tx * 4];
            u64 b0 = pack2(b.x), b1 = pack2(b.y), b2 = pack2(b.z), b3 = pack2(b.w);
            ffma2(acc[0][0], A01.x, b0); ffma2(acc[0][1], A01.x, b1);
            ffma2(acc[0][2], A01.x, b2); ffma2(acc[0][3], A01.x, b3);
            ffma2(acc[1][0], A01.y, b0); ffma2(acc[1][1], A01.y, b1);
            ffma2(acc[1][2], A01.y, b2); ffma2(acc[1][3], A01.y, b3);
            ffma2(acc[2][0], A23.x, b0); ffma2(acc[2][1], A23.x, b1);
            ffma2(acc[2][2], A23.x, b2); ffma2(acc[2][3], A23.x, b3);
            ffma2(acc[3][0], A23.y, b0); ffma2(acc[3][1], A23.y, b1);
            ffma2(acc[3][2], A23.y, b2); ffma2(acc[3][3], A23.y, b3);
        }
        __syncthreads();
    }
#pragma unroll
    for (int p = 0; p < 4; p++) {
        float2 f0 = *(float2*)&acc[p][0];
        float2 f1 = *(float2*)&acc[p][1];
        float2 f2 = *(float2*)&acc[p][2];
        float2 f3 = *(float2*)&acc[p][3];
        int r0 = bm + ty * 8 + 2 * p;
        if (r0 < M)
            *(float4*)&C[(size_t)r0 * Ncol + bn + tx * 4] =
                make_float4(f0.x, f1.x, f2.x, f3.x);
        if (r0 + 1 < M)
            *(float4*)&C[(size_t)(r0 + 1) * Ncol + bn + tx * 4] =
                make_float4(f0.y, f1.y, f2.y, f3.y);
    }
}

// ---------------- alpha kernels ----------------
__global__ __launch_bounds__(256)
void alpha1_kernel(const float* __restrict__ att_src, const float* __restrict__ att_dst,
                   int nnodes) {
    int gid = blockIdx.x * blockDim.x + threadIdx.x;
    if (gid >= nnodes * 8) return;
    int n = gid >> 3, h = gid & 7;
    const float4* hp = (const float4*)&g_h1[n * 64 + h * 8];
    float4 h0 = hp[0], h1v = hp[1];
    const float4* sp = (const float4*)&att_src[h * 8];
    const float4* dp = (const float4*)&att_dst[h * 8];
    float4 s0 = sp[0], s1v = sp[1];
    float4 d0 = dp[0], d1v = dp[1];
    float as = h0.x * s0.x + h0.y * s0.y + h0.z * s0.z + h0.w * s0.w
             + h1v.x * s1v.x + h1v.y * s1v.y + h1v.z * s1v.z + h1v.w * s1v.w;
    float ad = h0.x * d0.x + h0.y * d0.y + h0.z * d0.z + h0.w * d0.w
             + h1v.x * d1v.x + h1v.y * d1v.y + h1v.z * d1v.z + h1v.w * d1v.w;
    g_as1[gid] = as;
    g_ad1[gid] = ad;
}

__global__ __launch_bounds__(256)
void alpha2_kernel(const float* __restrict__ att_src, const float* __restrict__ att_dst,
                   int nnodes) {
    int gid = blockIdx.x * blockDim.x + threadIdx.x;
    int n = gid >> 5;
    int lane = gid & 31;
    if (n >= nnodes) return;
    float4 v = *(const float4*)&g_h2[(size_t)n * 128 + lane * 4];
    float4 a = ((const float4*)att_src)[lane];
    float4 b = ((const float4*)att_dst)[lane];
    float ss = v.x * a.x + v.y * a.y + v.z * a.z + v.w * a.w;
    float dd = v.x * b.x + v.y * b.y + v.z * b.z + v.w * b.w;
#pragma unroll
    for (int off = 16; off > 0; off >>= 1) {
        ss += __shfl_xor_sync(0xFFFFFFFFu, ss, off);
        dd += __shfl_xor_sync(0xFFFFFFFFu, dd, off);
    }
    if (lane == 0) { g_as2[n] = ss; g_ad2[n] = dd; }
}

// ---------------- aggregations (warp per destination node) ----------------
__global__ __launch_bounds__(256)
void agg1_kernel(const float* __restrict__ b1, int nnodes) {
    int gw = (blockIdx.x * 256 + threadIdx.x) >> 5;
    int lane = threadIdx.x & 31;
    if (gw >= nnodes) return;
    int h = lane >> 2;
    float ad = g_ad1[gw * 8 + h];
    int beg = g_off[gw], end = g_off[gw + 1];
    float ax = 0.f, ay = 0.f, denom = 0.f;
    for (int j = beg; j < end; j++) {
        int s = g_csr[j];
        float w = __expf(leaky(g_as1[s * 8 + h] + ad));
        float2 v = *(const float2*)&g_h1[s * 64 + lane * 2];
        ax += w * v.x; ay += w * v.y; denom += w;
    }
    float inv = 1.0f / denom;
    int c = lane * 2;
    float o0 = ax * inv + b1[c];
    float o1 = ay * inv + b1[c + 1];
    o0 = o0 > 0.f ? o0 : expm1f(o0);
    o1 = o1 > 0.f ? o1 : expm1f(o1);
    *(float2*)&g_hmid[gw * 64 + c] = make_float2(o0, o1);
}

__global__ __launch_bounds__(256)
void agg2_kernel(const float* __restrict__ b2, float* __restrict__ out, int nnodes) {
    int gw = (blockIdx.x * 256 + threadIdx.x) >> 5;
    int lane = threadIdx.x & 31;
    if (gw >= nnodes) return;
    float ad = g_ad2[gw];
    int beg = g_off[gw], end = g_off[gw + 1];
    float4 acc = make_float4(0.f, 0.f, 0.f, 0.f);
    float denom = 0.f;
    for (int j = beg; j < end; j++) {
        int s = g_csr[j];
        float w = __expf(leaky(g_as2[s] + ad));
        float4 v = *(const float4*)&g_h2[(size_t)s * 128 + lane * 4];
        acc.x += w * v.x; acc.y += w * v.y; acc.z += w * v.z; acc.w += w * v.w;
        denom += w;
    }
    float inv = 1.0f / denom;
    float4 bb = ((const float4*)b2)[lane];
    float4 o = make_float4(acc.x * inv + bb.x, acc.y * inv + bb.y,
                           acc.z * inv + bb.z, acc.w * inv + bb.w);
    *(float4*)&out[(size_t)gw * 128 + lane * 4] = o;
}

// ---------------- launcher ----------------
static cudaStream_t g_side = nullptr;
static cudaEvent_t  g_ev_fork = nullptr, g_ev_csr = nullptr;

extern "C" void kernel_launch(void* const* d_in, const int* in_sizes, int n_in,
                              void* d_out, int out_size) {
    const float* x        = (const float*)d_in[0];
    const int*   ei       = (const int*)d_in[1];
    const float* W1       = (const float*)d_in[2];
    const float* att_src1 = (const float*)d_in[3];
    const float* att_dst1 = (const float*)d_in[4];
    const float* b1       = (const float*)d_in[5];
    const float* W2       = (const float*)d_in[6];
    const float* att_src2 = (const float*)d_in[7];
    const float* att_dst2 = (const float*)d_in[8];
    const float* b2       = (const float*)d_in[9];
    float* out = (float*)d_out;

    const int nnodes = in_sizes[0] / 512;
    const int E      = in_sizes[1] / 2;
    const int Etot   = E + nnodes;
    const int T = 256;
    const int NB = (nnodes + 1023) / 1024;

    if (!g_side) {   // one-time infra (created on the uncaptured correctness call)
        cudaStreamCreateWithFlags(&g_side, cudaStreamNonBlocking);
        cudaEventCreateWithFlags(&g_ev_fork, cudaEventDisableTiming);
        cudaEventCreateWithFlags(&g_ev_csr,  cudaEventDisableTiming);
    }

    void* pcnt; cudaGetSymbolAddress(&pcnt, g_cnt);
    float *h1_ptr, *hmid_ptr, *h2_ptr;
    cudaGetSymbolAddress((void**)&h1_ptr, g_h1);
    cudaGetSymbolAddress((void**)&hmid_ptr, g_hmid);
    cudaGetSymbolAddress((void**)&h2_ptr, g_h2);

    // ---- fork: CSR build on side stream, GEMM1+alpha1 on main stream ----
    cudaEventRecord(g_ev_fork, 0);
    cudaStreamWaitEvent(g_side, g_ev_fork, 0);

    cudaMemsetAsync(pcnt, 0, (size_t)nnodes * 4, g_side);
    hist_kernel<<<(Etot + T - 1) / T, T, 0, g_side>>>(ei, E, Etot);
    scan1_kernel<<<NB, T, 0, g_side>>>(nnodes);
    scan2_kernel<<<1, 32, 0, g_side>>>(NB, nnodes);
    scan3_kernel<<<(nnodes + T - 1) / T, T, 0, g_side>>>(nnodes);
    cudaMemsetAsync(pcnt, 0, (size_t)nnodes * 4, g_side);
    scatter_kernel<<<(Etot + T - 1) / T, T, 0, g_side>>>(ei, E, Etot);
    cudaEventRecord(g_ev_csr, g_side);

    dim3 g1grid((nnodes + 127) / 128, 1);
    gemm_kernel<<<g1grid, T>>>(x, W1, h1_ptr, nnodes, 512, 64);
    alpha1_kernel<<<(nnodes * 8 + T - 1) / T, T>>>(att_src1, att_dst1, nnodes);

    // ---- join, then the rest is serial on the main stream ----
    cudaStreamWaitEvent(0, g_ev_csr, 0);
    agg1_kernel<<<((size_t)nnodes * 32 + T - 1) / T, T>>>(b1, nnodes);

    dim3 g2grid((nnodes + 127) / 128, 2);
    gemm_kernel<<<g2grid, T>>>(hmid_ptr, W2, h2_ptr, nnodes, 64, 128);
    alpha2_kernel<<<((size_t)nnodes * 32 + T - 1) / T, T>>>(att_src2, att_dst2, nnodes);
    agg2_kernel<<<((size_t)nnodes * 32 + T - 1) / T, T>>>(b2, out, nnodes);
}